// round 14
// baseline (speedup 1.0000x reference)
#include <cuda_runtime.h>
#include <cuda_fp16.h>
#include <math.h>
#include <stdint.h>

#define DDIM 256
#define NROWS 8192
#define BN 128                      // cols per CTA
#define BK 64                       // fp16 k per A chunk
#define ACH 16384                   // A stage bytes: 128 rows * 128B (swizzled)
#define SMB (3 * ACH)               // B region offset = 49152
#define BBYTES (BN * 512)           // B resident: 128 rows * 512B = 65536
#define SMEM_TOTAL (SMB + BBYTES)   // 114688 -> 2 CTAs/SM

// -------------------- scratch --------------------
__device__ __half g_Ah[NROWS * DDIM];   // x1 * sqrt(alpha), fp16
__device__ __half g_Bh[NROWS * DDIM];   // x2 * sqrt(alpha), fp16
__device__ float g_n1[NROWS];
__device__ float g_n2[NROWS];

// -------------------- helpers --------------------
__device__ __forceinline__ uint32_t smem_u32(const void* p) {
    uint32_t a;
    asm("{ .reg .u64 t; cvta.to.shared.u64 t, %1; cvt.u32.u64 %0, t; }" : "=r"(a) : "l"(p));
    return a;
}
__device__ __forceinline__ void cp_async16(uint32_t saddr, const void* g) {
    asm volatile("cp.async.cg.shared.global [%0], [%1], 16;" :: "r"(saddr), "l"(g));
}
__device__ __forceinline__ void ldmatrix_x4(uint32_t* r, uint32_t saddr) {
    asm volatile("ldmatrix.sync.aligned.m8n8.x4.shared.b16 {%0,%1,%2,%3}, [%4];"
                 : "=r"(r[0]), "=r"(r[1]), "=r"(r[2]), "=r"(r[3]) : "r"(saddr));
}
__device__ __forceinline__ void mma_f16(float* c, const uint32_t* a, const uint32_t* b) {
    asm("mma.sync.aligned.m16n8k16.row.col.f32.f16.f16.f32 "
        "{%0,%1,%2,%3}, {%4,%5,%6,%7}, {%8,%9}, {%0,%1,%2,%3};"
        : "+f"(c[0]), "+f"(c[1]), "+f"(c[2]), "+f"(c[3])
        : "r"(a[0]), "r"(a[1]), "r"(a[2]), "r"(a[3]), "r"(b[0]), "r"(b[1]));
}

// -------------------- prep: block-local softmax + scale + norms ------------
__global__ void prep_kernel(const float* __restrict__ x1,
                            const float* __restrict__ x2,
                            const float* __restrict__ alpha_raw,
                            __half* __restrict__ Ah,
                            __half* __restrict__ Bh,
                            float* __restrict__ n1,
                            float* __restrict__ n2,
                            int N) {
    __shared__ float sh[DDIM];
    __shared__ float sas[DDIM];
    const int d = threadIdx.x;

    float t = alpha_raw[d] * alpha_raw[d];
    sh[d] = t;
    __syncthreads();
    #pragma unroll
    for (int s = 128; s > 0; s >>= 1) {
        if (d < s) sh[d] = fmaxf(sh[d], sh[d + s]);
        __syncthreads();
    }
    float mx = sh[0];
    __syncthreads();
    float e = expf(t - mx);
    sh[d] = e;
    __syncthreads();
    #pragma unroll
    for (int s = 128; s > 0; s >>= 1) {
        if (d < s) sh[d] += sh[d + s];
        __syncthreads();
    }
    sas[d] = sqrtf(e / sh[0]);
    __syncthreads();

    const int w = blockIdx.x * 8 + (threadIdx.x >> 5);
    const int lane = threadIdx.x & 31;
    const float* src;
    __half* dst;
    if (w < N) { src = x1 + (size_t)w * DDIM; dst = Ah + (size_t)w * DDIM; }
    else       { src = x2 + (size_t)(w - N) * DDIM; dst = Bh + (size_t)(w - N) * DDIM; }

    float s = 0.0f;
    #pragma unroll
    for (int j = 0; j < 2; j++) {
        const int c = j * 128 + lane * 4;
        float4 xv = *(const float4*)(src + c);
        float4 sv = *(const float4*)(sas + c);
        float v0 = xv.x * sv.x, v1 = xv.y * sv.y, v2 = xv.z * sv.z, v3 = xv.w * sv.w;
        __half h[4] = { __float2half(v0), __float2half(v1),
                        __float2half(v2), __float2half(v3) };
        *(uint2*)(dst + c) = *(const uint2*)h;
        s += v0 * v0 + v1 * v1 + v2 * v2 + v3 * v3;
    }
    #pragma unroll
    for (int o = 16; o > 0; o >>= 1)
        s += __shfl_xor_sync(0xFFFFFFFFu, s, o);
    if (lane == 0) {
        if (w < N) n1[w] = s;
        else       n2[w - N] = s;
    }
}

// -------------------- fused HMMA GEMM + RBF epilogue --------------------
// 256 threads (8 warps: 2 in M x 4 in N), warp tile 64x32. CTA output =
// 256x128 as two sequential 128x128 passes; B (128 rows x K=256, 64KB)
// resident in smem across passes; A streams in 8 chunks via 3-stage ring.
// XOR swizzle (chunk ^ (row&7)); fill leads compute by 2 groups.
__global__ void __launch_bounds__(256, 2)
rbf_mma_kernel(const __half* __restrict__ Ah,
               const __half* __restrict__ Bh,
               const float* __restrict__ n1,
               const float* __restrict__ n2,
               const float* __restrict__ variance_raw,
               float* __restrict__ out,
               int Mcols) {
    extern __shared__ char smem[];
    const uint32_t sbase = smem_u32(smem);
    const int tid = threadIdx.x;
    const int wid = tid >> 5;
    const int lane = tid & 31;
    const int wm = wid & 1;       // 2 warps in M, 64 rows each (per pass)
    const int wn = wid >> 1;      // 4 warps in N, 32 cols each
    const int row0 = blockIdx.y * 256;
    const int col0 = blockIdx.x * BN;

    float acc[4][4][4];
    #pragma unroll
    for (int i = 0; i < 4; i++)
        #pragma unroll
        for (int j = 0; j < 4; j++)
            #pragma unroll
            for (int q = 0; q < 4; q++) acc[i][j][q] = 0.0f;

    // ---- A fill geometry: 1024 16B-chunks per stage / 256 thr = 4 each ----
    uint32_t soffA[4], goffA[4];
    #pragma unroll
    for (int l = 0; l < 4; l++) {
        int u = tid + l * 256;
        int r = u >> 3, c = u & 7;
        soffA[l] = (uint32_t)(r * 128 + ((c ^ (r & 7)) << 4));
        goffA[l] = (uint32_t)(r * DDIM + c * 8);    // element offset
    }
    const __half* abase = Ah + (size_t)row0 * DDIM;

    // ---- B fill (once): warp wid covers rows wid+8l; r&7 == wid ----
    {
        const __half* bsrc = Bh + (size_t)(col0 + wid) * DDIM + lane * 8;
        const uint32_t bcol = (uint32_t)((lane ^ wid) << 4);
        #pragma unroll
        for (int l = 0; l < 16; l++) {
            const int r = wid + l * 8;
            cp_async16(sbase + SMB + (uint32_t)(r * 512) + bcol,
                       bsrc + (size_t)l * 8 * DDIM);
        }
    }

#define FILLA(j) do {                                                          \
        const uint32_t stb_ = sbase + ((j) % 3) * ACH;                         \
        const size_t go_ = (size_t)((j) >> 2) * 128 * DDIM + ((j) & 3) * BK;   \
        _Pragma("unroll")                                                      \
        for (int l = 0; l < 4; l++)                                            \
            cp_async16(stb_ + soffA[l], abase + goffA[l] + go_);               \
        asm volatile("cp.async.commit_group;" ::: "memory");                   \
    } while (0)

    FILLA(0);            // group 0 = B + A0
    FILLA(1);            // group 1 = A1

    // ---- ldmatrix bases ----
    const int lrow = lane & 15;
    const int hb = lane >> 4;
    const uint32_t s74 = (uint32_t)((lrow & 7) << 4);
    uint32_t arow[4], brow[2];
    #pragma unroll
    for (int mt = 0; mt < 4; mt++)
        arow[mt] = sbase + (uint32_t)((wm * 64 + mt * 16 + lrow) * 128);
    #pragma unroll
    for (int t = 0; t < 2; t++)
        brow[t] = sbase + SMB + (uint32_t)((wn * 32 + t * 16 + lrow) * 512);

    uint32_t af[4][4], bf[4][2];

#define LOAD_FRAGS(stoff, jk, ks) do {                                         \
        const uint32_t ac_ = ((uint32_t)(((ks) * 2 + hb) << 4)) ^ s74;         \
        const uint32_t bc_ = ((uint32_t)((((jk) * 8) + (ks) * 2 + hb) << 4)) ^ s74; \
        _Pragma("unroll")                                                      \
        for (int mt = 0; mt < 4; mt++)                                         \
            ldmatrix_x4(af[mt], (stoff) + arow[mt] + ac_);                     \
        _Pragma("unroll")                                                      \
        for (int t = 0; t < 2; t++) {                                          \
            uint32_t rr[4];                                                    \
            ldmatrix_x4(rr, brow[t] + bc_);                                    \
            bf[t * 2][0] = rr[0]; bf[t * 2][1] = rr[2];                        \
            bf[t * 2 + 1][0] = rr[1]; bf[t * 2 + 1][1] = rr[3];                \
        }                                                                      \
    } while (0)

    const float vr = variance_raw[0];
    const float var = vr * vr;
    const int qrow = lane >> 2;
    const int qcol = (lane & 3) * 2;

#define EPILOGUE(prow) do {                                                    \
        _Pragma("unroll")                                                      \
        for (int mt = 0; mt < 4; mt++) {                                       \
            const int rg = (prow) + wm * 64 + mt * 16 + qrow;                  \
            const float rnA = n1[rg];                                          \
            const float rnB = n1[rg + 8];                                      \
            _Pragma("unroll")                                                  \
            for (int nt = 0; nt < 4; nt++) {                                   \
                const int cg = col0 + wn * 32 + nt * 8 + qcol;                 \
                float2 nn = *(const float2*)(n2 + cg);                         \
                float sq0 = fmaxf(fmaf(-2.0f, acc[mt][nt][0], rnA + nn.x), 0.0f); \
                float sq1 = fmaxf(fmaf(-2.0f, acc[mt][nt][1], rnA + nn.y), 0.0f); \
                float sq2 = fmaxf(fmaf(-2.0f, acc[mt][nt][2], rnB + nn.x), 0.0f); \
                float sq3 = fmaxf(fmaf(-2.0f, acc[mt][nt][3], rnB + nn.y), 0.0f); \
                float2 v0 = make_float2(var * __expf(-0.5f * sq0),             \
                                        var * __expf(-0.5f * sq1));            \
                float2 v1 = make_float2(var * __expf(-0.5f * sq2),             \
                                        var * __expf(-0.5f * sq3));            \
                *(float2*)(out + (size_t)rg * Mcols + cg) = v0;                \
                *(float2*)(out + (size_t)(rg + 8) * Mcols + cg) = v1;          \
                acc[mt][nt][0] = 0.0f; acc[mt][nt][1] = 0.0f;                  \
                acc[mt][nt][2] = 0.0f; acc[mt][nt][3] = 0.0f;                  \
            }                                                                  \
        }                                                                      \
    } while (0)

    #pragma unroll
    for (int j = 0; j < 8; j++) {
        if (j < 7) asm volatile("cp.async.wait_group 1;" ::: "memory");
        else       asm volatile("cp.async.wait_group 0;" ::: "memory");
        __syncthreads();

        if (j + 2 < 8) FILLA(j + 2);

        const uint32_t stoff = (uint32_t)((j % 3) * ACH);
        const int jk = j & 3;

        #pragma unroll
        for (int ks = 0; ks < 4; ks++) {
            LOAD_FRAGS(stoff, jk, ks);
            #pragma unroll
            for (int mt = 0; mt < 4; mt++)
                #pragma unroll
                for (int nt = 0; nt < 4; nt++)
                    mma_f16(acc[mt][nt], af[mt], bf[nt]);
        }

        if (j == 3) {
            // pass-0 epilogue: overlaps in-flight A chunks 4,5 for pass 1
            EPILOGUE(row0);
        }
    }
    EPILOGUE(row0 + 128);

#undef FILLA
#undef LOAD_FRAGS
#undef EPILOGUE
}

// -------------------- launch --------------------
extern "C" void kernel_launch(void* const* d_in, const int* in_sizes, int n_in,
                              void* d_out, int out_size) {
    const float* x1 = (const float*)d_in[0];
    const float* x2 = (const float*)d_in[1];
    const float* alpha_raw = (const float*)d_in[2];
    const float* variance_raw = (const float*)d_in[3];
    float* out = (float*)d_out;

    int N = in_sizes[0] / DDIM;
    int M = in_sizes[1] / DDIM;

    __half *Ah, *Bh;
    float *n1, *n2;
    cudaGetSymbolAddress((void**)&Ah, g_Ah);
    cudaGetSymbolAddress((void**)&Bh, g_Bh);
    cudaGetSymbolAddress((void**)&n1, g_n1);
    cudaGetSymbolAddress((void**)&n2, g_n2);

    cudaFuncSetAttribute(rbf_mma_kernel, cudaFuncAttributeMaxDynamicSharedMemorySize, SMEM_TOTAL);

    prep_kernel<<<(N + M) / 8, 256>>>(x1, x2, alpha_raw, Ah, Bh, n1, n2, N);

    dim3 grid(M / BN, N / 256);
    rbf_mma_kernel<<<grid, 256, SMEM_TOTAL>>>(Ah, Bh, n1, n2, variance_raw, out, M);
}

// round 15
// speedup vs baseline: 1.0278x; 1.0278x over previous
#include <cuda_runtime.h>
#include <cuda_fp16.h>
#include <math.h>
#include <stdint.h>

#define DDIM 256
#define NROWS 8192
#define BN 128                      // cols per CTA
#define BK 64                       // fp16 k per A chunk
#define ACH 16384                   // A stage bytes: 128 rows * 128B (swizzled)
#define SMB (3 * ACH)               // B region offset = 49152
#define BBYTES (BN * 512)           // B resident: 128 rows * 512B = 65536
#define SMEM_TOTAL (SMB + BBYTES)   // 114688 -> 2 CTAs/SM

// -------------------- scratch --------------------
__device__ __half g_Ah[NROWS * DDIM];   // x1 * sqrt(alpha), fp16
__device__ __half g_Bh[NROWS * DDIM];   // x2 * sqrt(alpha), fp16
__device__ float g_n1[NROWS];
__device__ float g_n2[NROWS];

// -------------------- helpers --------------------
__device__ __forceinline__ uint32_t smem_u32(const void* p) {
    uint32_t a;
    asm("{ .reg .u64 t; cvta.to.shared.u64 t, %1; cvt.u32.u64 %0, t; }" : "=r"(a) : "l"(p));
    return a;
}
__device__ __forceinline__ void cp_async16(uint32_t saddr, const void* g) {
    asm volatile("cp.async.cg.shared.global [%0], [%1], 16;" :: "r"(saddr), "l"(g));
}
__device__ __forceinline__ void ldmatrix_x4(uint32_t* r, uint32_t saddr) {
    asm volatile("ldmatrix.sync.aligned.m8n8.x4.shared.b16 {%0,%1,%2,%3}, [%4];"
                 : "=r"(r[0]), "=r"(r[1]), "=r"(r[2]), "=r"(r[3]) : "r"(saddr));
}
__device__ __forceinline__ void mma_f16(float* c, const uint32_t* a, const uint32_t* b) {
    asm("mma.sync.aligned.m16n8k16.row.col.f32.f16.f16.f32 "
        "{%0,%1,%2,%3}, {%4,%5,%6,%7}, {%8,%9}, {%0,%1,%2,%3};"
        : "+f"(c[0]), "+f"(c[1]), "+f"(c[2]), "+f"(c[3])
        : "r"(a[0]), "r"(a[1]), "r"(a[2]), "r"(a[3]), "r"(b[0]), "r"(b[1]));
}
__device__ __forceinline__ float ex2f(float x) {
    float y;
    asm("ex2.approx.ftz.f32 %0, %1;" : "=f"(y) : "f"(x));
    return y;
}

// -------------------- prep: block-local softmax + scale + norms ------------
__global__ void prep_kernel(const float* __restrict__ x1,
                            const float* __restrict__ x2,
                            const float* __restrict__ alpha_raw,
                            __half* __restrict__ Ah,
                            __half* __restrict__ Bh,
                            float* __restrict__ n1,
                            float* __restrict__ n2,
                            int N) {
    __shared__ float sh[DDIM];
    __shared__ float sas[DDIM];
    const int d = threadIdx.x;

    float t = alpha_raw[d] * alpha_raw[d];
    sh[d] = t;
    __syncthreads();
    #pragma unroll
    for (int s = 128; s > 0; s >>= 1) {
        if (d < s) sh[d] = fmaxf(sh[d], sh[d + s]);
        __syncthreads();
    }
    float mx = sh[0];
    __syncthreads();
    float e = expf(t - mx);
    sh[d] = e;
    __syncthreads();
    #pragma unroll
    for (int s = 128; s > 0; s >>= 1) {
        if (d < s) sh[d] += sh[d + s];
        __syncthreads();
    }
    sas[d] = sqrtf(e / sh[0]);
    __syncthreads();

    const int w = blockIdx.x * 8 + (threadIdx.x >> 5);
    const int lane = threadIdx.x & 31;
    const float* src;
    __half* dst;
    if (w < N) { src = x1 + (size_t)w * DDIM; dst = Ah + (size_t)w * DDIM; }
    else       { src = x2 + (size_t)(w - N) * DDIM; dst = Bh + (size_t)(w - N) * DDIM; }

    float s = 0.0f;
    #pragma unroll
    for (int j = 0; j < 2; j++) {
        const int c = j * 128 + lane * 4;
        float4 xv = *(const float4*)(src + c);
        float4 sv = *(const float4*)(sas + c);
        float v0 = xv.x * sv.x, v1 = xv.y * sv.y, v2 = xv.z * sv.z, v3 = xv.w * sv.w;
        __half h[4] = { __float2half(v0), __float2half(v1),
                        __float2half(v2), __float2half(v3) };
        *(uint2*)(dst + c) = *(const uint2*)h;
        s += v0 * v0 + v1 * v1 + v2 * v2 + v3 * v3;
    }
    #pragma unroll
    for (int o = 16; o > 0; o >>= 1)
        s += __shfl_xor_sync(0xFFFFFFFFu, s, o);
    if (lane == 0) {
        if (w < N) n1[w] = s;
        else       n2[w - N] = s;
    }
}

// -------------------- fused HMMA GEMM + RBF epilogue --------------------
// 256 threads (8 warps: 2 in M x 4 in N), warp tile 64x32. CTA output =
// 256x128 as two sequential 128x128 passes; B (128 rows x K=256, 64KB)
// resident in smem across passes; A streams in 8 chunks via 3-stage ring.
// XOR swizzle (chunk ^ (row&7)); fill leads compute by 2 groups.
// Epilogue: var*exp(-sq/2) folded to ex2(min(c1*sq + c2, c2)).
__global__ void __launch_bounds__(256, 2)
rbf_mma_kernel(const __half* __restrict__ Ah,
               const __half* __restrict__ Bh,
               const float* __restrict__ n1,
               const float* __restrict__ n2,
               const float* __restrict__ variance_raw,
               float* __restrict__ out,
               int Mcols) {
    extern __shared__ char smem[];
    const uint32_t sbase = smem_u32(smem);
    const int tid = threadIdx.x;
    const int wid = tid >> 5;
    const int lane = tid & 31;
    const int wm = wid & 1;       // 2 warps in M, 64 rows each (per pass)
    const int wn = wid >> 1;      // 4 warps in N, 32 cols each
    const int row0 = blockIdx.y * 256;
    const int col0 = blockIdx.x * BN;

    float acc[4][4][4];
    #pragma unroll
    for (int i = 0; i < 4; i++)
        #pragma unroll
        for (int j = 0; j < 4; j++)
            #pragma unroll
            for (int q = 0; q < 4; q++) acc[i][j][q] = 0.0f;

    // ---- A fill geometry: 1024 16B-chunks per stage / 256 thr = 4 each ----
    uint32_t soffA[4], goffA[4];
    #pragma unroll
    for (int l = 0; l < 4; l++) {
        int u = tid + l * 256;
        int r = u >> 3, c = u & 7;
        soffA[l] = (uint32_t)(r * 128 + ((c ^ (r & 7)) << 4));
        goffA[l] = (uint32_t)(r * DDIM + c * 8);    // element offset
    }
    const __half* abase = Ah + (size_t)row0 * DDIM;

    // ---- B fill (once): warp wid covers rows wid+8l; r&7 == wid ----
    {
        const __half* bsrc = Bh + (size_t)(col0 + wid) * DDIM + lane * 8;
        const uint32_t bcol = (uint32_t)((lane ^ wid) << 4);
        #pragma unroll
        for (int l = 0; l < 16; l++) {
            const int r = wid + l * 8;
            cp_async16(sbase + SMB + (uint32_t)(r * 512) + bcol,
                       bsrc + (size_t)l * 8 * DDIM);
        }
    }

#define FILLA(j) do {                                                          \
        const uint32_t stb_ = sbase + ((j) % 3) * ACH;                         \
        const size_t go_ = (size_t)((j) >> 2) * 128 * DDIM + ((j) & 3) * BK;   \
        _Pragma("unroll")                                                      \
        for (int l = 0; l < 4; l++)                                            \
            cp_async16(stb_ + soffA[l], abase + goffA[l] + go_);               \
        asm volatile("cp.async.commit_group;" ::: "memory");                   \
    } while (0)

    FILLA(0);            // group 0 = B + A0
    FILLA(1);            // group 1 = A1

    // ---- ldmatrix bases ----
    const int lrow = lane & 15;
    const int hb = lane >> 4;
    const uint32_t s74 = (uint32_t)((lrow & 7) << 4);
    uint32_t arow[4], brow[2];
    #pragma unroll
    for (int mt = 0; mt < 4; mt++)
        arow[mt] = sbase + (uint32_t)((wm * 64 + mt * 16 + lrow) * 128);
    #pragma unroll
    for (int t = 0; t < 2; t++)
        brow[t] = sbase + SMB + (uint32_t)((wn * 32 + t * 16 + lrow) * 512);

    // hoisted swizzled k-offsets: kx[ks] = ((ks*2+hb)<<4) ^ s74
    uint32_t kx[4];
    #pragma unroll
    for (int ks = 0; ks < 4; ks++)
        kx[ks] = ((uint32_t)((ks * 2 + hb) << 4)) ^ s74;

    uint32_t af[4][4], bf[4][2];

#define LOAD_FRAGS(stoff, jk, ks) do {                                         \
        const uint32_t bko_ = (uint32_t)((jk) * 128) + kx[ks];                 \
        _Pragma("unroll")                                                      \
        for (int mt = 0; mt < 4; mt++)                                         \
            ldmatrix_x4(af[mt], (stoff) + arow[mt] + kx[ks]);                  \
        _Pragma("unroll")                                                      \
        for (int t = 0; t < 2; t++) {                                          \
            uint32_t rr[4];                                                    \
            ldmatrix_x4(rr, brow[t] + bko_);                                   \
            bf[t * 2][0] = rr[0]; bf[t * 2][1] = rr[2];                        \
            bf[t * 2 + 1][0] = rr[1]; bf[t * 2 + 1][1] = rr[3];                \
        }                                                                      \
    } while (0)

    const float vr = variance_raw[0];
    const float c1 = -0.72134752f;          // -0.5 * log2(e)
    const float c2 = __log2f(vr * vr);      // log2(var); var=0 -> -inf -> out 0
    const int qrow = lane >> 2;
    const int qcol = (lane & 3) * 2;

#define EPILOGUE(prow) do {                                                    \
        _Pragma("unroll")                                                      \
        for (int mt = 0; mt < 4; mt++) {                                       \
            const int rg = (prow) + wm * 64 + mt * 16 + qrow;                  \
            const float rnA = n1[rg];                                          \
            const float rnB = n1[rg + 8];                                      \
            _Pragma("unroll")                                                  \
            for (int nt = 0; nt < 4; nt++) {                                   \
                const int cg = col0 + wn * 32 + nt * 8 + qcol;                 \
                float2 nn = *(const float2*)(n2 + cg);                         \
                float sq0 = fmaf(-2.0f, acc[mt][nt][0], rnA + nn.x);           \
                float sq1 = fmaf(-2.0f, acc[mt][nt][1], rnA + nn.y);           \
                float sq2 = fmaf(-2.0f, acc[mt][nt][2], rnB + nn.x);           \
                float sq3 = fmaf(-2.0f, acc[mt][nt][3], rnB + nn.y);           \
                float2 v0 = make_float2(ex2f(fminf(fmaf(c1, sq0, c2), c2)),    \
                                        ex2f(fminf(fmaf(c1, sq1, c2), c2)));   \
                float2 v1 = make_float2(ex2f(fminf(fmaf(c1, sq2, c2), c2)),    \
                                        ex2f(fminf(fmaf(c1, sq3, c2), c2)));   \
                *(float2*)(out + (size_t)rg * Mcols + cg) = v0;                \
                *(float2*)(out + (size_t)(rg + 8) * Mcols + cg) = v1;          \
                acc[mt][nt][0] = 0.0f; acc[mt][nt][1] = 0.0f;                  \
                acc[mt][nt][2] = 0.0f; acc[mt][nt][3] = 0.0f;                  \
            }                                                                  \
        }                                                                      \
    } while (0)

    #pragma unroll
    for (int j = 0; j < 8; j++) {
        if (j < 7) asm volatile("cp.async.wait_group 1;" ::: "memory");
        else       asm volatile("cp.async.wait_group 0;" ::: "memory");
        __syncthreads();

        if (j + 2 < 8) FILLA(j + 2);

        const uint32_t stoff = (uint32_t)((j % 3) * ACH);
        const int jk = j & 3;

        #pragma unroll
        for (int ks = 0; ks < 4; ks++) {
            LOAD_FRAGS(stoff, jk, ks);
            #pragma unroll
            for (int mt = 0; mt < 4; mt++)
                #pragma unroll
                for (int nt = 0; nt < 4; nt++)
                    mma_f16(acc[mt][nt], af[mt], bf[nt]);
        }

        if (j == 3) {
            // pass-0 epilogue: overlaps in-flight A chunks 4,5 for pass 1
            EPILOGUE(row0);
        }
    }
    EPILOGUE(row0 + 128);

#undef FILLA
#undef LOAD_FRAGS
#undef EPILOGUE
}

// -------------------- launch --------------------
extern "C" void kernel_launch(void* const* d_in, const int* in_sizes, int n_in,
                              void* d_out, int out_size) {
    const float* x1 = (const float*)d_in[0];
    const float* x2 = (const float*)d_in[1];
    const float* alpha_raw = (const float*)d_in[2];
    const float* variance_raw = (const float*)d_in[3];
    float* out = (float*)d_out;

    int N = in_sizes[0] / DDIM;
    int M = in_sizes[1] / DDIM;

    __half *Ah, *Bh;
    float *n1, *n2;
    cudaGetSymbolAddress((void**)&Ah, g_Ah);
    cudaGetSymbolAddress((void**)&Bh, g_Bh);
    cudaGetSymbolAddress((void**)&n1, g_n1);
    cudaGetSymbolAddress((void**)&n2, g_n2);

    cudaFuncSetAttribute(rbf_mma_kernel, cudaFuncAttributeMaxDynamicSharedMemorySize, SMEM_TOTAL);

    prep_kernel<<<(N + M) / 8, 256>>>(x1, x2, alpha_raw, Ah, Bh, n1, n2, N);

    dim3 grid(M / BN, N / 256);
    rbf_mma_kernel<<<grid, 256, SMEM_TOTAL>>>(Ah, Bh, n1, n2, variance_raw, out, M);
}

// round 16
// speedup vs baseline: 1.0417x; 1.0136x over previous
#include <cuda_runtime.h>
#include <cuda_fp16.h>
#include <math.h>
#include <stdint.h>

#define DDIM 256
#define NROWS 8192
#define BN 128                      // cols per CTA
#define BK 64                       // fp16 k per A chunk
#define ACH 16384                   // A stage bytes: 128 rows * 128B (swizzled)
#define SMB (3 * ACH)               // B region offset = 49152
#define BBYTES (BN * 512)           // B resident: 128 rows * 512B = 65536
#define SMEM_TOTAL (SMB + BBYTES)   // 114688 -> 2 CTAs/SM

// -------------------- scratch --------------------
__device__ __half g_Ah[NROWS * DDIM];   // x1 * sqrt(alpha), fp16
__device__ __half g_Bh[NROWS * DDIM];   // x2 * sqrt(alpha), fp16
__device__ float g_n1[NROWS];
__device__ float g_n2[NROWS];

// -------------------- helpers --------------------
__device__ __forceinline__ uint32_t smem_u32(const void* p) {
    uint32_t a;
    asm("{ .reg .u64 t; cvta.to.shared.u64 t, %1; cvt.u32.u64 %0, t; }" : "=r"(a) : "l"(p));
    return a;
}
__device__ __forceinline__ void cp_async16(uint32_t saddr, const void* g) {
    asm volatile("cp.async.cg.shared.global [%0], [%1], 16;" :: "r"(saddr), "l"(g));
}
__device__ __forceinline__ void ldmatrix_x4(uint32_t* r, uint32_t saddr) {
    asm volatile("ldmatrix.sync.aligned.m8n8.x4.shared.b16 {%0,%1,%2,%3}, [%4];"
                 : "=r"(r[0]), "=r"(r[1]), "=r"(r[2]), "=r"(r[3]) : "r"(saddr));
}
__device__ __forceinline__ void mma_f16(float* c, const uint32_t* a, const uint32_t* b) {
    asm("mma.sync.aligned.m16n8k16.row.col.f32.f16.f16.f32 "
        "{%0,%1,%2,%3}, {%4,%5,%6,%7}, {%8,%9}, {%0,%1,%2,%3};"
        : "+f"(c[0]), "+f"(c[1]), "+f"(c[2]), "+f"(c[3])
        : "r"(a[0]), "r"(a[1]), "r"(a[2]), "r"(a[3]), "r"(b[0]), "r"(b[1]));
}
__device__ __forceinline__ float ex2f(float x) {
    float y;
    asm("ex2.approx.ftz.f32 %0, %1;" : "=f"(y) : "f"(x));
    return y;
}
// streaming (evict-first) store: keeps the 256MB output stream from evicting
// the hot 8MB A/B working set out of L2.
__device__ __forceinline__ void stg_cs_v2(float* p, float x, float y) {
    asm volatile("st.global.cs.v2.f32 [%0], {%1, %2};" :: "l"(p), "f"(x), "f"(y) : "memory");
}

// -------------------- prep: block-local softmax + scale + norms ------------
__global__ void prep_kernel(const float* __restrict__ x1,
                            const float* __restrict__ x2,
                            const float* __restrict__ alpha_raw,
                            __half* __restrict__ Ah,
                            __half* __restrict__ Bh,
                            float* __restrict__ n1,
                            float* __restrict__ n2,
                            int N) {
    __shared__ float sh[DDIM];
    __shared__ float sas[DDIM];
    const int d = threadIdx.x;

    float t = alpha_raw[d] * alpha_raw[d];
    sh[d] = t;
    __syncthreads();
    #pragma unroll
    for (int s = 128; s > 0; s >>= 1) {
        if (d < s) sh[d] = fmaxf(sh[d], sh[d + s]);
        __syncthreads();
    }
    float mx = sh[0];
    __syncthreads();
    float e = expf(t - mx);
    sh[d] = e;
    __syncthreads();
    #pragma unroll
    for (int s = 128; s > 0; s >>= 1) {
        if (d < s) sh[d] += sh[d + s];
        __syncthreads();
    }
    sas[d] = sqrtf(e / sh[0]);
    __syncthreads();

    const int w = blockIdx.x * 8 + (threadIdx.x >> 5);
    const int lane = threadIdx.x & 31;
    const float* src;
    __half* dst;
    if (w < N) { src = x1 + (size_t)w * DDIM; dst = Ah + (size_t)w * DDIM; }
    else       { src = x2 + (size_t)(w - N) * DDIM; dst = Bh + (size_t)(w - N) * DDIM; }

    float s = 0.0f;
    #pragma unroll
    for (int j = 0; j < 2; j++) {
        const int c = j * 128 + lane * 4;
        float4 xv = *(const float4*)(src + c);
        float4 sv = *(const float4*)(sas + c);
        float v0 = xv.x * sv.x, v1 = xv.y * sv.y, v2 = xv.z * sv.z, v3 = xv.w * sv.w;
        __half h[4] = { __float2half(v0), __float2half(v1),
                        __float2half(v2), __float2half(v3) };
        *(uint2*)(dst + c) = *(const uint2*)h;
        s += v0 * v0 + v1 * v1 + v2 * v2 + v3 * v3;
    }
    #pragma unroll
    for (int o = 16; o > 0; o >>= 1)
        s += __shfl_xor_sync(0xFFFFFFFFu, s, o);
    if (lane == 0) {
        if (w < N) n1[w] = s;
        else       n2[w - N] = s;
    }
}

// -------------------- fused HMMA GEMM + RBF epilogue --------------------
// 256 threads (8 warps: 2 in M x 4 in N), warp tile 64x32. CTA output =
// 256x128 as two sequential 128x128 passes; B (128 rows x K=256, 64KB)
// resident in smem across passes; A streams in 8 chunks via 3-stage ring.
// XOR swizzle (chunk ^ (row&7)); fill leads compute by 2 groups.
// Epilogue: var*exp(-sq/2) folded to ex2(min(c1*sq + c2, c2)); .cs stores.
__global__ void __launch_bounds__(256, 2)
rbf_mma_kernel(const __half* __restrict__ Ah,
               const __half* __restrict__ Bh,
               const float* __restrict__ n1,
               const float* __restrict__ n2,
               const float* __restrict__ variance_raw,
               float* __restrict__ out,
               int Mcols) {
    extern __shared__ char smem[];
    const uint32_t sbase = smem_u32(smem);
    const int tid = threadIdx.x;
    const int wid = tid >> 5;
    const int lane = tid & 31;
    const int wm = wid & 1;       // 2 warps in M, 64 rows each (per pass)
    const int wn = wid >> 1;      // 4 warps in N, 32 cols each
    const int row0 = blockIdx.y * 256;
    const int col0 = blockIdx.x * BN;

    float acc[4][4][4];
    #pragma unroll
    for (int i = 0; i < 4; i++)
        #pragma unroll
        for (int j = 0; j < 4; j++)
            #pragma unroll
            for (int q = 0; q < 4; q++) acc[i][j][q] = 0.0f;

    // ---- A fill geometry: 1024 16B-chunks per stage / 256 thr = 4 each ----
    uint32_t soffA[4], goffA[4];
    #pragma unroll
    for (int l = 0; l < 4; l++) {
        int u = tid + l * 256;
        int r = u >> 3, c = u & 7;
        soffA[l] = (uint32_t)(r * 128 + ((c ^ (r & 7)) << 4));
        goffA[l] = (uint32_t)(r * DDIM + c * 8);    // element offset
    }
    const __half* abase = Ah + (size_t)row0 * DDIM;

    // ---- B fill (once): warp wid covers rows wid+8l; r&7 == wid ----
    {
        const __half* bsrc = Bh + (size_t)(col0 + wid) * DDIM + lane * 8;
        const uint32_t bcol = (uint32_t)((lane ^ wid) << 4);
        #pragma unroll
        for (int l = 0; l < 16; l++) {
            const int r = wid + l * 8;
            cp_async16(sbase + SMB + (uint32_t)(r * 512) + bcol,
                       bsrc + (size_t)l * 8 * DDIM);
        }
    }

#define FILLA(j) do {                                                          \
        const uint32_t stb_ = sbase + ((j) % 3) * ACH;                         \
        const size_t go_ = (size_t)((j) >> 2) * 128 * DDIM + ((j) & 3) * BK;   \
        _Pragma("unroll")                                                      \
        for (int l = 0; l < 4; l++)                                            \
            cp_async16(stb_ + soffA[l], abase + goffA[l] + go_);               \
        asm volatile("cp.async.commit_group;" ::: "memory");                   \
    } while (0)

    FILLA(0);            // group 0 = B + A0
    FILLA(1);            // group 1 = A1

    // ---- ldmatrix bases ----
    const int lrow = lane & 15;
    const int hb = lane >> 4;
    const uint32_t s74 = (uint32_t)((lrow & 7) << 4);
    uint32_t arow[4], brow[2];
    #pragma unroll
    for (int mt = 0; mt < 4; mt++)
        arow[mt] = sbase + (uint32_t)((wm * 64 + mt * 16 + lrow) * 128);
    #pragma unroll
    for (int t = 0; t < 2; t++)
        brow[t] = sbase + SMB + (uint32_t)((wn * 32 + t * 16 + lrow) * 512);

    // hoisted swizzled k-offsets: kx[ks] = ((ks*2+hb)<<4) ^ s74
    uint32_t kx[4];
    #pragma unroll
    for (int ks = 0; ks < 4; ks++)
        kx[ks] = ((uint32_t)((ks * 2 + hb) << 4)) ^ s74;

    uint32_t af[4][4], bf[4][2];

#define LOAD_FRAGS(stoff, jk, ks) do {                                         \
        const uint32_t bko_ = (uint32_t)((jk) * 128) + kx[ks];                 \
        _Pragma("unroll")                                                      \
        for (int mt = 0; mt < 4; mt++)                                         \
            ldmatrix_x4(af[mt], (stoff) + arow[mt] + kx[ks]);                  \
        _Pragma("unroll")                                                      \
        for (int t = 0; t < 2; t++) {                                          \
            uint32_t rr[4];                                                    \
            ldmatrix_x4(rr, brow[t] + bko_);                                   \
            bf[t * 2][0] = rr[0]; bf[t * 2][1] = rr[2];                        \
            bf[t * 2 + 1][0] = rr[1]; bf[t * 2 + 1][1] = rr[3];                \
        }                                                                      \
    } while (0)

    const float vr = variance_raw[0];
    const float c1 = -0.72134752f;          // -0.5 * log2(e)
    const float c2 = __log2f(vr * vr);      // log2(var); var=0 -> -inf -> out 0
    const int qrow = lane >> 2;
    const int qcol = (lane & 3) * 2;

#define EPILOGUE(prow) do {                                                    \
        _Pragma("unroll")                                                      \
        for (int mt = 0; mt < 4; mt++) {                                       \
            const int rg = (prow) + wm * 64 + mt * 16 + qrow;                  \
            const float rnA = n1[rg];                                          \
            const float rnB = n1[rg + 8];                                      \
            _Pragma("unroll")                                                  \
            for (int nt = 0; nt < 4; nt++) {                                   \
                const int cg = col0 + wn * 32 + nt * 8 + qcol;                 \
                float2 nn = *(const float2*)(n2 + cg);                         \
                float sq0 = fmaf(-2.0f, acc[mt][nt][0], rnA + nn.x);           \
                float sq1 = fmaf(-2.0f, acc[mt][nt][1], rnA + nn.y);           \
                float sq2 = fmaf(-2.0f, acc[mt][nt][2], rnB + nn.x);           \
                float sq3 = fmaf(-2.0f, acc[mt][nt][3], rnB + nn.y);           \
                stg_cs_v2(out + (size_t)rg * Mcols + cg,                       \
                          ex2f(fminf(fmaf(c1, sq0, c2), c2)),                  \
                          ex2f(fminf(fmaf(c1, sq1, c2), c2)));                 \
                stg_cs_v2(out + (size_t)(rg + 8) * Mcols + cg,                 \
                          ex2f(fminf(fmaf(c1, sq2, c2), c2)),                  \
                          ex2f(fminf(fmaf(c1, sq3, c2), c2)));                 \
                acc[mt][nt][0] = 0.0f; acc[mt][nt][1] = 0.0f;                  \
                acc[mt][nt][2] = 0.0f; acc[mt][nt][3] = 0.0f;                  \
            }                                                                  \
        }                                                                      \
    } while (0)

    #pragma unroll
    for (int j = 0; j < 8; j++) {
        if (j < 7) asm volatile("cp.async.wait_group 1;" ::: "memory");
        else       asm volatile("cp.async.wait_group 0;" ::: "memory");
        __syncthreads();

        if (j + 2 < 8) FILLA(j + 2);

        const uint32_t stoff = (uint32_t)((j % 3) * ACH);
        const int jk = j & 3;

        #pragma unroll
        for (int ks = 0; ks < 4; ks++) {
            LOAD_FRAGS(stoff, jk, ks);
            #pragma unroll
            for (int mt = 0; mt < 4; mt++)
                #pragma unroll
                for (int nt = 0; nt < 4; nt++)
                    mma_f16(acc[mt][nt], af[mt], bf[nt]);
        }

        if (j == 3) {
            // pass-0 epilogue: overlaps in-flight A chunks 4,5 for pass 1
            EPILOGUE(row0);
        }
    }
    EPILOGUE(row0 + 128);

#undef FILLA
#undef LOAD_FRAGS
#undef EPILOGUE
}

// -------------------- launch --------------------
extern "C" void kernel_launch(void* const* d_in, const int* in_sizes, int n_in,
                              void* d_out, int out_size) {
    const float* x1 = (const float*)d_in[0];
    const float* x2 = (const float*)d_in[1];
    const float* alpha_raw = (const float*)d_in[2];
    const float* variance_raw = (const float*)d_in[3];
    float* out = (float*)d_out;

    int N = in_sizes[0] / DDIM;
    int M = in_sizes[1] / DDIM;

    __half *Ah, *Bh;
    float *n1, *n2;
    cudaGetSymbolAddress((void**)&Ah, g_Ah);
    cudaGetSymbolAddress((void**)&Bh, g_Bh);
    cudaGetSymbolAddress((void**)&n1, g_n1);
    cudaGetSymbolAddress((void**)&n2, g_n2);

    cudaFuncSetAttribute(rbf_mma_kernel, cudaFuncAttributeMaxDynamicSharedMemorySize, SMEM_TOTAL);

    prep_kernel<<<(N + M) / 8, 256>>>(x1, x2, alpha_raw, Ah, Bh, n1, n2, N);

    dim3 grid(M / BN, N / 256);
    rbf_mma_kernel<<<grid, 256, SMEM_TOTAL>>>(Ah, Bh, n1, n2, variance_raw, out, M);
}

// round 17
// speedup vs baseline: 1.0614x; 1.0189x over previous
#include <cuda_runtime.h>
#include <cuda_fp16.h>
#include <math.h>
#include <stdint.h>

#define DDIM 256
#define NROWS 8192
#define BN 128                      // cols per CTA
#define BK 64                       // fp16 k per A chunk
#define ACH 16384                   // A stage bytes: 128 rows * 128B (swizzled)
#define SMB (3 * ACH)               // B region offset = 49152
#define BBYTES (BN * 512)           // B resident: 128 rows * 512B = 65536
#define SMEM_TOTAL (SMB + BBYTES)   // 114688 -> 2 CTAs/SM

// -------------------- scratch --------------------
__device__ __half g_Ah[NROWS * DDIM];   // x1 * sqrt(alpha), fp16
__device__ __half g_Bh[NROWS * DDIM];   // x2 * sqrt(alpha), fp16
__device__ float g_n1[NROWS];
__device__ float g_n2[NROWS];

// -------------------- helpers --------------------
__device__ __forceinline__ uint32_t smem_u32(const void* p) {
    uint32_t a;
    asm("{ .reg .u64 t; cvta.to.shared.u64 t, %1; cvt.u32.u64 %0, t; }" : "=r"(a) : "l"(p));
    return a;
}
__device__ __forceinline__ void cp_async16(uint32_t saddr, const void* g) {
    asm volatile("cp.async.cg.shared.global [%0], [%1], 16;" :: "r"(saddr), "l"(g));
}
__device__ __forceinline__ void ldmatrix_x4(uint32_t* r, uint32_t saddr) {
    asm volatile("ldmatrix.sync.aligned.m8n8.x4.shared.b16 {%0,%1,%2,%3}, [%4];"
                 : "=r"(r[0]), "=r"(r[1]), "=r"(r[2]), "=r"(r[3]) : "r"(saddr));
}
__device__ __forceinline__ void ldmatrix_x2(uint32_t* r, uint32_t saddr) {
    asm volatile("ldmatrix.sync.aligned.m8n8.x2.shared.b16 {%0,%1}, [%2];"
                 : "=r"(r[0]), "=r"(r[1]) : "r"(saddr));
}
__device__ __forceinline__ void mma_f16(float* c, const uint32_t* a, const uint32_t* b) {
    asm("mma.sync.aligned.m16n8k16.row.col.f32.f16.f16.f32 "
        "{%0,%1,%2,%3}, {%4,%5,%6,%7}, {%8,%9}, {%0,%1,%2,%3};"
        : "+f"(c[0]), "+f"(c[1]), "+f"(c[2]), "+f"(c[3])
        : "r"(a[0]), "r"(a[1]), "r"(a[2]), "r"(a[3]), "r"(b[0]), "r"(b[1]));
}
__device__ __forceinline__ float ex2f(float x) {
    float y;
    asm("ex2.approx.ftz.f32 %0, %1;" : "=f"(y) : "f"(x));
    return y;
}
__device__ __forceinline__ void stg_cs_v2(float* p, float x, float y) {
    asm volatile("st.global.cs.v2.f32 [%0], {%1, %2};" :: "l"(p), "f"(x), "f"(y) : "memory");
}

// -------------------- prep: block-local softmax + scale + norms ------------
// 256 threads/block; each warp handles TWO rows (blocks = (N+M)/16).
__global__ void prep_kernel(const float* __restrict__ x1,
                            const float* __restrict__ x2,
                            const float* __restrict__ alpha_raw,
                            __half* __restrict__ Ah,
                            __half* __restrict__ Bh,
                            float* __restrict__ n1,
                            float* __restrict__ n2,
                            int N) {
    __shared__ float sh[DDIM];
    __shared__ float sas[DDIM];
    const int d = threadIdx.x;

    float t = alpha_raw[d] * alpha_raw[d];
    sh[d] = t;
    __syncthreads();
    #pragma unroll
    for (int s = 128; s > 0; s >>= 1) {
        if (d < s) sh[d] = fmaxf(sh[d], sh[d + s]);
        __syncthreads();
    }
    float mx = sh[0];
    __syncthreads();
    float e = expf(t - mx);
    sh[d] = e;
    __syncthreads();
    #pragma unroll
    for (int s = 128; s > 0; s >>= 1) {
        if (d < s) sh[d] += sh[d + s];
        __syncthreads();
    }
    sas[d] = sqrtf(e / sh[0]);
    __syncthreads();

    const int lane = threadIdx.x & 31;
    #pragma unroll
    for (int rr = 0; rr < 2; rr++) {
        const int w = blockIdx.x * 16 + (threadIdx.x >> 5) * 2 + rr;
        const float* src;
        __half* dst;
        if (w < N) { src = x1 + (size_t)w * DDIM; dst = Ah + (size_t)w * DDIM; }
        else       { src = x2 + (size_t)(w - N) * DDIM; dst = Bh + (size_t)(w - N) * DDIM; }

        float s = 0.0f;
        #pragma unroll
        for (int j = 0; j < 2; j++) {
            const int c = j * 128 + lane * 4;
            float4 xv = *(const float4*)(src + c);
            float4 sv = *(const float4*)(sas + c);
            float v0 = xv.x * sv.x, v1 = xv.y * sv.y, v2 = xv.z * sv.z, v3 = xv.w * sv.w;
            __half h[4] = { __float2half(v0), __float2half(v1),
                            __float2half(v2), __float2half(v3) };
            *(uint2*)(dst + c) = *(const uint2*)h;
            s += v0 * v0 + v1 * v1 + v2 * v2 + v3 * v3;
        }
        #pragma unroll
        for (int o = 16; o > 0; o >>= 1)
            s += __shfl_xor_sync(0xFFFFFFFFu, s, o);
        if (lane == 0) {
            if (w < N) n1[w] = s;
            else       n2[w - N] = s;
        }
    }
}

// -------------------- fused HMMA GEMM + RBF epilogue --------------------
// 256 threads (8 warps: 2 in M x 4 in N), warp tile 64x32. CTA output =
// 256x128 as two 128x128 passes; B resident in smem; A 3-stage ring.
// bf double-buffered: next k-step's B LDSMs issue between current MMAs.
__global__ void __launch_bounds__(256, 2)
rbf_mma_kernel(const __half* __restrict__ Ah,
               const __half* __restrict__ Bh,
               const float* __restrict__ n1,
               const float* __restrict__ n2,
               const float* __restrict__ variance_raw,
               float* __restrict__ out,
               int Mcols) {
    extern __shared__ char smem[];
    const uint32_t sbase = smem_u32(smem);
    const int tid = threadIdx.x;
    const int wid = tid >> 5;
    const int lane = tid & 31;
    const int wm = wid & 1;       // 2 warps in M, 64 rows each (per pass)
    const int wn = wid >> 1;      // 4 warps in N, 32 cols each
    // raster swizzle: 4-wide column groups -> concurrent CTAs share B slices
    const int bid = blockIdx.x;           // 0..2047 (flattened 64 x 32)
    const int grp = bid >> 7;             // 16 groups of 128 CTAs
    const int within = bid & 127;
    const int tx = grp * 4 + (within & 3);    // col tile 0..63
    const int ty = within >> 2;               // row tile 0..31
    const int row0 = ty * 256;
    const int col0 = tx * BN;

    float acc[4][4][4];
    #pragma unroll
    for (int i = 0; i < 4; i++)
        #pragma unroll
        for (int j = 0; j < 4; j++)
            #pragma unroll
            for (int q = 0; q < 4; q++) acc[i][j][q] = 0.0f;

    // ---- A fill geometry ----
    uint32_t soffA[4], goffA[4];
    #pragma unroll
    for (int l = 0; l < 4; l++) {
        int u = tid + l * 256;
        int r = u >> 3, c = u & 7;
        soffA[l] = (uint32_t)(r * 128 + ((c ^ (r & 7)) << 4));
        goffA[l] = (uint32_t)(r * DDIM + c * 8);
    }
    const __half* abase = Ah + (size_t)row0 * DDIM;

    // ---- B fill (once) ----
    {
        const __half* bsrc = Bh + (size_t)(col0 + wid) * DDIM + lane * 8;
        const uint32_t bcol = (uint32_t)((lane ^ wid) << 4);
        #pragma unroll
        for (int l = 0; l < 16; l++) {
            const int r = wid + l * 8;
            cp_async16(sbase + SMB + (uint32_t)(r * 512) + bcol,
                       bsrc + (size_t)l * 8 * DDIM);
        }
    }

#define FILLA(j) do {                                                          \
        const uint32_t stb_ = sbase + ((j) % 3) * ACH;                         \
        const size_t go_ = (size_t)((j) >> 2) * 128 * DDIM + ((j) & 3) * BK;   \
        _Pragma("unroll")                                                      \
        for (int l = 0; l < 4; l++)                                            \
            cp_async16(stb_ + soffA[l], abase + goffA[l] + go_);               \
        asm volatile("cp.async.commit_group;" ::: "memory");                   \
    } while (0)

    FILLA(0);
    FILLA(1);

    // ---- ldmatrix bases ----
    const int lrow = lane & 15;
    const int hb = lane >> 4;
    const uint32_t s74 = (uint32_t)((lrow & 7) << 4);
    uint32_t arow[4], brow[2];
    #pragma unroll
    for (int mt = 0; mt < 4; mt++)
        arow[mt] = sbase + (uint32_t)((wm * 64 + mt * 16 + lrow) * 128);
    #pragma unroll
    for (int t = 0; t < 2; t++)
        brow[t] = sbase + SMB + (uint32_t)((wn * 32 + t * 16 + lrow) * 512);

    uint32_t kx[4];
    #pragma unroll
    for (int ks = 0; ks < 4; ks++)
        kx[ks] = ((uint32_t)((ks * 2 + hb) << 4)) ^ s74;

    uint32_t af[4][4], bf[2][4][2];

#define LOAD_B(buf, jk, ks) do {                                               \
        const uint32_t bko_ = (uint32_t)((jk) * 128) + kx[ks];                 \
        _Pragma("unroll")                                                      \
        for (int t = 0; t < 2; t++) {                                          \
            uint32_t rr[4];                                                    \
            ldmatrix_x4(rr, brow[t] + bko_);                                   \
            bf[buf][t * 2][0] = rr[0]; bf[buf][t * 2][1] = rr[2];              \
            bf[buf][t * 2 + 1][0] = rr[1]; bf[buf][t * 2 + 1][1] = rr[3];      \
        }                                                                      \
    } while (0)

#define LOAD_A(stoff, ks) do {                                                 \
        _Pragma("unroll")                                                      \
        for (int mt = 0; mt < 4; mt++)                                         \
            ldmatrix_x4(af[mt], (stoff) + arow[mt] + kx[ks]);                  \
    } while (0)

    const float vr = variance_raw[0];
    const float c1 = -0.72134752f;          // -0.5 * log2(e)
    const float c2 = __log2f(vr * vr);      // log2(var)
    const int qrow = lane >> 2;
    const int qcol = (lane & 3) * 2;

#define EPILOGUE(prow) do {                                                    \
        _Pragma("unroll")                                                      \
        for (int mt = 0; mt < 4; mt++) {                                       \
            const int rg = (prow) + wm * 64 + mt * 16 + qrow;                  \
            const float rnA = n1[rg];                                          \
            const float rnB = n1[rg + 8];                                      \
            _Pragma("unroll")                                                  \
            for (int nt = 0; nt < 4; nt++) {                                   \
                const int cg = col0 + wn * 32 + nt * 8 + qcol;                 \
                float2 nn = *(const float2*)(n2 + cg);                         \
                float sq0 = fmaf(-2.0f, acc[mt][nt][0], rnA + nn.x);           \
                float sq1 = fmaf(-2.0f, acc[mt][nt][1], rnA + nn.y);           \
                float sq2 = fmaf(-2.0f, acc[mt][nt][2], rnB + nn.x);           \
                float sq3 = fmaf(-2.0f, acc[mt][nt][3], rnB + nn.y);           \
                stg_cs_v2(out + (size_t)rg * Mcols + cg,                       \
                          ex2f(fminf(fmaf(c1, sq0, c2), c2)),                  \
                          ex2f(fminf(fmaf(c1, sq1, c2), c2)));                 \
                stg_cs_v2(out + (size_t)(rg + 8) * Mcols + cg,                 \
                          ex2f(fminf(fmaf(c1, sq2, c2), c2)),                  \
                          ex2f(fminf(fmaf(c1, sq3, c2), c2)));                 \
                acc[mt][nt][0] = 0.0f; acc[mt][nt][1] = 0.0f;                  \
                acc[mt][nt][2] = 0.0f; acc[mt][nt][3] = 0.0f;                  \
            }                                                                  \
        }                                                                      \
    } while (0)

    #pragma unroll
    for (int j = 0; j < 8; j++) {
        if (j < 7) asm volatile("cp.async.wait_group 1;" ::: "memory");
        else       asm volatile("cp.async.wait_group 0;" ::: "memory");
        __syncthreads();

        if (j + 2 < 8) FILLA(j + 2);

        const uint32_t stoff = (uint32_t)((j % 3) * ACH);
        const int jk = j & 3;

        LOAD_B(0, jk, 0);
        #pragma unroll
        for (int ks = 0; ks < 4; ks++) {
            LOAD_A(stoff, ks);
            if (ks < 3) LOAD_B((ks + 1) & 1, jk, ks + 1);   // prefetch next B
            const int cb = ks & 1;
            #pragma unroll
            for (int mt = 0; mt < 4; mt++)
                #pragma unroll
                for (int nt = 0; nt < 4; nt++)
                    mma_f16(acc[mt][nt], af[mt], bf[cb][nt]);
        }

        if (j == 3) {
            EPILOGUE(row0);
        }
    }
    EPILOGUE(row0 + 128);

#undef FILLA
#undef LOAD_A
#undef LOAD_B
#undef EPILOGUE
}

// -------------------- launch --------------------
extern "C" void kernel_launch(void* const* d_in, const int* in_sizes, int n_in,
                              void* d_out, int out_size) {
    const float* x1 = (const float*)d_in[0];
    const float* x2 = (const float*)d_in[1];
    const float* alpha_raw = (const float*)d_in[2];
    const float* variance_raw = (const float*)d_in[3];
    float* out = (float*)d_out;

    int N = in_sizes[0] / DDIM;
    int M = in_sizes[1] / DDIM;

    __half *Ah, *Bh;
    float *n1, *n2;
    cudaGetSymbolAddress((void**)&Ah, g_Ah);
    cudaGetSymbolAddress((void**)&Bh, g_Bh);
    cudaGetSymbolAddress((void**)&n1, g_n1);
    cudaGetSymbolAddress((void**)&n2, g_n2);

    cudaFuncSetAttribute(rbf_mma_kernel, cudaFuncAttributeMaxDynamicSharedMemorySize, SMEM_TOTAL);

    prep_kernel<<<(N + M) / 16, 256>>>(x1, x2, alpha_raw, Ah, Bh, n1, n2, N);

    const int ntiles = (M / BN) * (N / 256);   // 2048
    rbf_mma_kernel<<<ntiles, 256, SMEM_TOTAL>>>(Ah, Bh, n1, n2, variance_raw, out, M);
}